// round 1
// baseline (speedup 1.0000x reference)
#include <cuda_runtime.h>

#define D_MODEL 1024
#define NHEAD   16
#define DHEAD   64
#define DFF_SZ  4096
#define BATCH   2
#define SEQ     2048
#define MROWS   (BATCH*SEQ)   // 4096

// ---------------- scratch (device globals; no allocations allowed) ----------
__device__ float g_q  [(size_t)MROWS * D_MODEL];
__device__ float g_k  [(size_t)MROWS * D_MODEL];
__device__ float g_v  [(size_t)MROWS * D_MODEL];
__device__ float g_ctx[(size_t)MROWS * D_MODEL];
__device__ float g_tmp[(size_t)MROWS * D_MODEL];
__device__ float g_x1 [(size_t)MROWS * D_MODEL];
__device__ float g_x2 [(size_t)MROWS * D_MODEL];
__device__ float g_ff [(size_t)MROWS * DFF_SZ];

// ---------------- SGEMM: C[M,N] = A[M,K] @ W[N,K]^T + bias, optional ReLU ----
template<bool RELU>
__global__ void __launch_bounds__(256, 2) sgemm_bias(
    const float* __restrict__ A, const float* __restrict__ W,
    const float* __restrict__ bias, float* __restrict__ C,
    int M, int N, int K)
{
    __shared__ float As[16 * 132];
    __shared__ float Bs[16 * 132];

    const int t  = threadIdx.x;
    const int lr = t >> 2;            // 0..63
    const int lc = (t & 3) << 2;      // 0,4,8,12
    const int ty = t >> 4;            // 0..15
    const int tx = t & 15;            // 0..15

    const float* Ab = A + ((size_t)blockIdx.y * 128 + lr) * K + lc;
    const float* Wb = W + ((size_t)blockIdx.x * 128 + lr) * K + lc;

    float acc[8][8];
#pragma unroll
    for (int i = 0; i < 8; i++)
#pragma unroll
        for (int j = 0; j < 8; j++) acc[i][j] = 0.f;

    for (int k0 = 0; k0 < K; k0 += 16) {
        float4 a0 = *(const float4*)(Ab + k0);
        float4 a1 = *(const float4*)(Ab + (size_t)64 * K + k0);
        float4 w0 = *(const float4*)(Wb + k0);
        float4 w1 = *(const float4*)(Wb + (size_t)64 * K + k0);
        __syncthreads();
        As[(lc + 0) * 132 + lr]      = a0.x;
        As[(lc + 1) * 132 + lr]      = a0.y;
        As[(lc + 2) * 132 + lr]      = a0.z;
        As[(lc + 3) * 132 + lr]      = a0.w;
        As[(lc + 0) * 132 + lr + 64] = a1.x;
        As[(lc + 1) * 132 + lr + 64] = a1.y;
        As[(lc + 2) * 132 + lr + 64] = a1.z;
        As[(lc + 3) * 132 + lr + 64] = a1.w;
        Bs[(lc + 0) * 132 + lr]      = w0.x;
        Bs[(lc + 1) * 132 + lr]      = w0.y;
        Bs[(lc + 2) * 132 + lr]      = w0.z;
        Bs[(lc + 3) * 132 + lr]      = w0.w;
        Bs[(lc + 0) * 132 + lr + 64] = w1.x;
        Bs[(lc + 1) * 132 + lr + 64] = w1.y;
        Bs[(lc + 2) * 132 + lr + 64] = w1.z;
        Bs[(lc + 3) * 132 + lr + 64] = w1.w;
        __syncthreads();

#pragma unroll
        for (int kk = 0; kk < 16; kk++) {
            float4 ra0 = *(const float4*)&As[kk * 132 + ty * 8];
            float4 ra1 = *(const float4*)&As[kk * 132 + ty * 8 + 4];
            float4 rb0 = *(const float4*)&Bs[kk * 132 + tx * 8];
            float4 rb1 = *(const float4*)&Bs[kk * 132 + tx * 8 + 4];
            float ra[8] = {ra0.x, ra0.y, ra0.z, ra0.w, ra1.x, ra1.y, ra1.z, ra1.w};
            float rb[8] = {rb0.x, rb0.y, rb0.z, rb0.w, rb1.x, rb1.y, rb1.z, rb1.w};
#pragma unroll
            for (int i = 0; i < 8; i++)
#pragma unroll
                for (int j = 0; j < 8; j++)
                    acc[i][j] = fmaf(ra[i], rb[j], acc[i][j]);
        }
    }

    const int row0 = blockIdx.y * 128 + ty * 8;
    const int col0 = blockIdx.x * 128 + tx * 8;
    float4 b0 = *(const float4*)(bias + col0);
    float4 b1 = *(const float4*)(bias + col0 + 4);
    float bb[8] = {b0.x, b0.y, b0.z, b0.w, b1.x, b1.y, b1.z, b1.w};
#pragma unroll
    for (int i = 0; i < 8; i++) {
        float o[8];
#pragma unroll
        for (int j = 0; j < 8; j++) {
            o[j] = acc[i][j] + bb[j];
            if (RELU) o[j] = fmaxf(o[j], 0.f);
        }
        *(float4*)(C + (size_t)(row0 + i) * N + col0)     = make_float4(o[0], o[1], o[2], o[3]);
        *(float4*)(C + (size_t)(row0 + i) * N + col0 + 4) = make_float4(o[4], o[5], o[6], o[7]);
    }
}

// ---------------- Fused attention (flash-style, 64x64 tiles, DK=64) ---------
// Q,K,V,O: [B*rows, D_MODEL] with head h at column h*64. mask: [B, SEQ, Skv] int.
#define PCH 68
__global__ void __launch_bounds__(256, 2) attn_kernel(
    const float* __restrict__ Q, const float* __restrict__ K,
    const float* __restrict__ V, const int* __restrict__ mask,
    float* __restrict__ O, int Skv, int causal)
{
    extern __shared__ float sm[];
    float* q_s = sm;                  // [64][PCH], transposed: q_s[d*PCH + r]
    float* k_s = sm + 64 * PCH;       // transposed: k_s[d*PCH + c]
    float* v_s = sm + 2 * 64 * PCH;   // v_s[c*PCH + d]
    float* p_s = sm + 3 * 64 * PCH;   // transposed: p_s[c*PCH + r]

    const int t  = threadIdx.x;
    const int ty = t >> 4;
    const int tx = t & 15;
    const int qt = blockIdx.x;
    const int h  = blockIdx.y;
    const int b  = blockIdx.z;

    const size_t qbase = ((size_t)(b * SEQ + qt * 64)) * D_MODEL + h * DHEAD;

    // load Q tile transposed (coalesced gmem reads)
#pragma unroll
    for (int e = 0; e < 16; e++) {
        int lin = e * 256 + t;
        int r = lin >> 6, d = lin & 63;
        q_s[d * PCH + r] = Q[qbase + (size_t)r * D_MODEL + d];
    }

    float m_i[4], l_i[4], o_acc[4][4];
#pragma unroll
    for (int i = 0; i < 4; i++) {
        m_i[i] = -1e30f;
        l_i[i] = 0.f;
#pragma unroll
        for (int j = 0; j < 4; j++) o_acc[i][j] = 0.f;
    }

    const int ntiles = causal ? (qt + 1) : (Skv >> 6);

    for (int jt = 0; jt < ntiles; jt++) {
        __syncthreads();   // protect prior-iteration reads of k_s/v_s/p_s
        const size_t kbase = ((size_t)(b * Skv + jt * 64)) * D_MODEL + h * DHEAD;
#pragma unroll
        for (int e = 0; e < 16; e++) {
            int lin = e * 256 + t;
            int r = lin >> 6, d = lin & 63;
            float kvv = K[kbase + (size_t)r * D_MODEL + d];
            float vvv = V[kbase + (size_t)r * D_MODEL + d];
            k_s[d * PCH + r] = kvv;
            v_s[r * PCH + d] = vvv;
        }
        __syncthreads();

        // S = Q K^T
        float s_acc[4][4];
#pragma unroll
        for (int i = 0; i < 4; i++)
#pragma unroll
            for (int j = 0; j < 4; j++) s_acc[i][j] = 0.f;

#pragma unroll 8
        for (int d = 0; d < 64; d++) {
            float4 qa = *(const float4*)&q_s[d * PCH + ty * 4];
            float4 kb = *(const float4*)&k_s[d * PCH + tx * 4];
            float qv[4] = {qa.x, qa.y, qa.z, qa.w};
            float kv[4] = {kb.x, kb.y, kb.z, kb.w};
#pragma unroll
            for (int i = 0; i < 4; i++)
#pragma unroll
                for (int j = 0; j < 4; j++)
                    s_acc[i][j] = fmaf(qv[i], kv[j], s_acc[i][j]);
        }

        // scale + mask + online softmax (row stats reduced over the 16 tx lanes)
#pragma unroll
        for (int i = 0; i < 4; i++) {
            int qg = qt * 64 + ty * 4 + i;
            const int* mp = mask + ((size_t)b * SEQ + qg) * Skv + jt * 64 + tx * 4;
            float tmax = -1e30f;
#pragma unroll
            for (int j = 0; j < 4; j++) {
                float s = s_acc[i][j] * 0.125f;
                if (mp[j] == 0) s = -1e9f;
                s_acc[i][j] = s;
                tmax = fmaxf(tmax, s);
            }
#pragma unroll
            for (int off = 1; off < 16; off <<= 1)
                tmax = fmaxf(tmax, __shfl_xor_sync(0xffffffffu, tmax, off));
            float newm = fmaxf(m_i[i], tmax);
            float rs = 0.f;
            float p[4];
#pragma unroll
            for (int j = 0; j < 4; j++) {
                p[j] = __expf(s_acc[i][j] - newm);
                rs += p[j];
            }
#pragma unroll
            for (int off = 1; off < 16; off <<= 1)
                rs += __shfl_xor_sync(0xffffffffu, rs, off);
            float alpha = __expf(m_i[i] - newm);
            l_i[i] = l_i[i] * alpha + rs;
            m_i[i] = newm;
#pragma unroll
            for (int j = 0; j < 4; j++) {
                o_acc[i][j] *= alpha;
                p_s[(tx * 4 + j) * PCH + ty * 4 + i] = p[j];
            }
        }
        __syncthreads();

        // O += P V
#pragma unroll 8
        for (int kv = 0; kv < 64; kv++) {
            float4 pv = *(const float4*)&p_s[kv * PCH + ty * 4];
            float4 vv = *(const float4*)&v_s[kv * PCH + tx * 4];
            float pr[4] = {pv.x, pv.y, pv.z, pv.w};
            float vr[4] = {vv.x, vv.y, vv.z, vv.w};
#pragma unroll
            for (int i = 0; i < 4; i++)
#pragma unroll
                for (int j = 0; j < 4; j++)
                    o_acc[i][j] = fmaf(pr[i], vr[j], o_acc[i][j]);
        }
    }

#pragma unroll
    for (int i = 0; i < 4; i++) {
        float inv = 1.f / l_i[i];
        size_t ob = qbase + (size_t)(ty * 4 + i) * D_MODEL + tx * 4;
        O[ob + 0] = o_acc[i][0] * inv;
        O[ob + 1] = o_acc[i][1] * inv;
        O[ob + 2] = o_acc[i][2] * inv;
        O[ob + 3] = o_acc[i][3] * inv;
    }
}

// ---------------- fused residual add + LayerNorm ----------------------------
__global__ void __launch_bounds__(256) add_ln_kernel(
    const float* __restrict__ a, const float* __restrict__ r,
    const float* __restrict__ g, const float* __restrict__ be,
    float* __restrict__ out)
{
    const int row = blockIdx.x;
    const int t = threadIdx.x;
    const size_t base = (size_t)row * D_MODEL;

    float4 va = *(const float4*)(a + base + t * 4);
    float4 vr = *(const float4*)(r + base + t * 4);
    float v[4] = {va.x + vr.x, va.y + vr.y, va.z + vr.z, va.w + vr.w};

    float s = v[0] + v[1] + v[2] + v[3];
    float q = v[0]*v[0] + v[1]*v[1] + v[2]*v[2] + v[3]*v[3];
#pragma unroll
    for (int off = 16; off >= 1; off >>= 1) {
        s += __shfl_down_sync(0xffffffffu, s, off);
        q += __shfl_down_sync(0xffffffffu, q, off);
    }
    __shared__ float shs[8], shq[8], fin[2];
    int w = t >> 5, lane = t & 31;
    if (lane == 0) { shs[w] = s; shq[w] = q; }
    __syncthreads();
    if (t == 0) {
        float as = 0.f, aq = 0.f;
#pragma unroll
        for (int i = 0; i < 8; i++) { as += shs[i]; aq += shq[i]; }
        fin[0] = as; fin[1] = aq;
    }
    __syncthreads();
    float mu  = fin[0] * (1.f / D_MODEL);
    float var = fin[1] * (1.f / D_MODEL) - mu * mu;
    float rstd = rsqrtf(var + 1e-5f);

    float4 vg = *(const float4*)(g + t * 4);
    float4 vb = *(const float4*)(be + t * 4);
    float4 o;
    o.x = (v[0] - mu) * rstd * vg.x + vb.x;
    o.y = (v[1] - mu) * rstd * vg.y + vb.y;
    o.z = (v[2] - mu) * rstd * vg.z + vb.z;
    o.w = (v[3] - mu) * rstd * vg.w + vb.w;
    *(float4*)(out + base + t * 4) = o;
}

// ---------------- launch ----------------------------------------------------
static void run_gemm(const float* A, const float* W, const float* b, float* C,
                     int M, int N, int K, bool relu)
{
    dim3 grid(N / 128, M / 128);
    if (relu) sgemm_bias<true><<<grid, 256>>>(A, W, b, C, M, N, K);
    else      sgemm_bias<false><<<grid, 256>>>(A, W, b, C, M, N, K);
}

extern "C" void kernel_launch(void* const* d_in, const int* in_sizes, int n_in,
                              void* d_out, int out_size)
{
    (void)in_sizes; (void)n_in; (void)out_size;
    const float* x    = (const float*)d_in[0];
    const float* enc  = (const float*)d_in[1];
    const int* src_mask = (const int*)d_in[2];
    const int* tgt_mask = (const int*)d_in[3];
    const float* sa_Wq = (const float*)d_in[4];
    const float* sa_bq = (const float*)d_in[5];
    const float* sa_Wk = (const float*)d_in[6];
    const float* sa_bk = (const float*)d_in[7];
    const float* sa_Wv = (const float*)d_in[8];
    const float* sa_bv = (const float*)d_in[9];
    const float* sa_Wo = (const float*)d_in[10];
    const float* sa_bo = (const float*)d_in[11];
    const float* ca_Wq = (const float*)d_in[12];
    const float* ca_bq = (const float*)d_in[13];
    const float* ca_Wk = (const float*)d_in[14];
    const float* ca_bk = (const float*)d_in[15];
    const float* ca_Wv = (const float*)d_in[16];
    const float* ca_bv = (const float*)d_in[17];
    const float* ca_Wo = (const float*)d_in[18];
    const float* ca_bo = (const float*)d_in[19];
    const float* ff_W1 = (const float*)d_in[20];
    const float* ff_b1 = (const float*)d_in[21];
    const float* ff_W2 = (const float*)d_in[22];
    const float* ff_b2 = (const float*)d_in[23];
    const float* ln1_g = (const float*)d_in[24];
    const float* ln1_b = (const float*)d_in[25];
    const float* ln2_g = (const float*)d_in[26];
    const float* ln2_b = (const float*)d_in[27];
    const float* ln3_g = (const float*)d_in[28];
    const float* ln3_b = (const float*)d_in[29];
    float* out = (float*)d_out;

    float *q, *k, *v, *ctx, *tmp, *x1, *x2, *ff;
    cudaGetSymbolAddress((void**)&q,   g_q);
    cudaGetSymbolAddress((void**)&k,   g_k);
    cudaGetSymbolAddress((void**)&v,   g_v);
    cudaGetSymbolAddress((void**)&ctx, g_ctx);
    cudaGetSymbolAddress((void**)&tmp, g_tmp);
    cudaGetSymbolAddress((void**)&x1,  g_x1);
    cudaGetSymbolAddress((void**)&x2,  g_x2);
    cudaGetSymbolAddress((void**)&ff,  g_ff);

    const int ATTN_SMEM = 4 * 64 * PCH * sizeof(float);
    cudaFuncSetAttribute(attn_kernel, cudaFuncAttributeMaxDynamicSharedMemorySize, ATTN_SMEM);

    dim3 agrid(SEQ / 64, NHEAD, BATCH);

    // ---- self-attention ----
    run_gemm(x, sa_Wq, sa_bq, q, MROWS, D_MODEL, D_MODEL, false);
    run_gemm(x, sa_Wk, sa_bk, k, MROWS, D_MODEL, D_MODEL, false);
    run_gemm(x, sa_Wv, sa_bv, v, MROWS, D_MODEL, D_MODEL, false);
    attn_kernel<<<agrid, 256, ATTN_SMEM>>>(q, k, v, tgt_mask, ctx, SEQ, 1);
    run_gemm(ctx, sa_Wo, sa_bo, tmp, MROWS, D_MODEL, D_MODEL, false);
    add_ln_kernel<<<MROWS, 256>>>(x, tmp, ln1_g, ln1_b, x1);

    // ---- cross-attention ----
    run_gemm(x1,  ca_Wq, ca_bq, q, MROWS, D_MODEL, D_MODEL, false);
    run_gemm(enc, ca_Wk, ca_bk, k, MROWS, D_MODEL, D_MODEL, false);
    run_gemm(enc, ca_Wv, ca_bv, v, MROWS, D_MODEL, D_MODEL, false);
    attn_kernel<<<agrid, 256, ATTN_SMEM>>>(q, k, v, src_mask, ctx, SEQ, 0);
    run_gemm(ctx, ca_Wo, ca_bo, tmp, MROWS, D_MODEL, D_MODEL, false);
    add_ln_kernel<<<MROWS, 256>>>(x1, tmp, ln2_g, ln2_b, x2);

    // ---- feed-forward ----
    run_gemm(x2, ff_W1, ff_b1, ff, MROWS, DFF_SZ, D_MODEL, true);
    run_gemm(ff, ff_W2, ff_b2, tmp, MROWS, D_MODEL, DFF_SZ, false);
    add_ln_kernel<<<MROWS, 256>>>(x2, tmp, ln3_g, ln3_b, out);
}